// round 16
// baseline (speedup 1.0000x reference)
#include <cuda_runtime.h>
#include <cuda_pipeline.h>
#include <math.h>
#include <stdint.h>

#define T_STEPS 1000
#define BATCH   64
#define IN_DIM  512
#define HID     1024
#define OUT_DIM 64
#define NY      65
#define E_SZ    819
#define ALPHA   0.2f
#define OMALPHA 0.8f
#define NCTA 128
#define OPAD 80
#define WSTR 1028            // j-row stride (floats) for weights AND staging

__device__ float g_xq[(size_t)T_STEPS * BATCH * HID];     // [t][b][h]
__device__ float g_outAll[(size_t)T_STEPS * HID * BATCH]; // [t][j][b]  (readout)
__device__ float g_outT[(size_t)T_STEPS * BATCH * HID];   // [t][b][j]  (rnn broadcast)
__device__ float g_eWhP2[32 * 32 * WSTR];                 // [hgrp][h&31][j pad]
__device__ float g_eWoT[HID * OPAD];                      // [j][o]
__device__ unsigned g_bar[8 * 64];                        // per-b-quarter count/flag (1000 flips, even)

__device__ __forceinline__ unsigned atom_add_release(unsigned* p, unsigned v) {
    unsigned r;
    asm volatile("atom.add.release.gpu.global.u32 %0, [%1], %2;"
                 : "=r"(r) : "l"(p), "r"(v) : "memory");
    return r;
}
__device__ __forceinline__ void st_relaxed(unsigned* p, unsigned v) {
    asm volatile("st.relaxed.gpu.global.u32 [%0], %1;" :: "l"(p), "r"(v) : "memory");
}
__device__ __forceinline__ void st_release(unsigned* p, unsigned v) {
    asm volatile("st.release.gpu.global.u32 [%0], %1;" :: "l"(p), "r"(v) : "memory");
}
__device__ __forceinline__ unsigned ld_acquire(unsigned* p) {
    unsigned r;
    asm volatile("ld.acquire.gpu.global.u32 %0, [%1];" : "=r"(r) : "l"(p) : "memory");
    return r;
}

__device__ __forceinline__ unsigned long long pk2(float x, float y) {
    unsigned long long r;
    asm("mov.b64 %0, {%1, %2};" : "=l"(r) : "r"(__float_as_uint(x)), "r"(__float_as_uint(y)));
    return r;
}
__device__ __forceinline__ void upk2(unsigned long long v, float &x, float &y) {
    unsigned xi, yi;
    asm("mov.b64 {%0, %1}, %2;" : "=r"(xi), "=r"(yi) : "l"(v));
    x = __uint_as_float(xi); y = __uint_as_float(yi);
}
__device__ __forceinline__ unsigned long long ffma2(unsigned long long a,
                                                    unsigned long long b,
                                                    unsigned long long c) {
    unsigned long long d;
    asm("fma.rn.f32x2 %0, %1, %2, %3;" : "=l"(d) : "l"(a), "l"(b), "l"(c));
    return d;
}
__device__ __forceinline__ unsigned long long fadd2(unsigned long long a,
                                                    unsigned long long b) {
    unsigned long long d;
    asm("add.rn.f32x2 %0, %1, %2;" : "=l"(d) : "l"(a), "l"(b));
    return d;
}

__global__ void noop_kernel() {}

__global__ void prep_kernel(const float* __restrict__ Wh,
                            const float* __restrict__ Wo,
                            const float* __restrict__ Wv) {
    int idx = blockIdx.x * blockDim.x + threadIdx.x;
    const int N1 = HID * HID;
    if (idx < N1) {
        int h = idx >> 10, j = idx & 1023;
        float v = Wh[idx];
        v = v > 0.f ? v : 0.f;
        float s = (j < E_SZ) ? 1.f : -1.f;
        v = (h == j) ? 0.f : v * s;
        g_eWhP2[(size_t)(h >> 5) * (32 * WSTR) + (size_t)(h & 31) * WSTR + j] = v;
    } else if (idx < N1 + NY * HID) {
        int i2 = idx - N1;
        int o = i2 >> 10, j = i2 & 1023;
        float v = (o < OUT_DIM) ? Wo[o * HID + j] : Wv[j];
        v = v > 0.f ? v : 0.f;
        if (j >= E_SZ) v = 0.f;
        g_eWoT[(size_t)j * OPAD + o] = v;
    }
}

// ---- phase 1 (proven): g_xq[t][b][h] = sum_k x[t][b][k]*relu(Wx[h][k])
__global__ __launch_bounds__(256) void xproj_kernel(const float* __restrict__ x,
                                                    const float* __restrict__ Wx) {
    __shared__ float As[16][64];
    __shared__ float Bs[16][128];
    const int t  = blockIdx.y;
    const int h0 = blockIdx.x * 128;
    const int tid = threadIdx.x;
    const int tx = tid & 15;
    const int ty = tid >> 4;

    unsigned long long acc[4][4];
#pragma unroll
    for (int i = 0; i < 4; i++)
#pragma unroll
        for (int p = 0; p < 4; p++) acc[i][p] = 0ull;

    const float* xb = x + (size_t)t * BATCH * IN_DIM;
    const int bb  = tid >> 2;
    const int kk4 = (tid & 3) << 2;
    const int hh  = tid & 127;
    const int kq  = (tid >> 7) << 3;

    for (int k0 = 0; k0 < IN_DIM; k0 += 16) {
        __syncthreads();
        float4 av = *(const float4*)&xb[(size_t)bb * IN_DIM + k0 + kk4];
        As[kk4 + 0][bb] = av.x; As[kk4 + 1][bb] = av.y;
        As[kk4 + 2][bb] = av.z; As[kk4 + 3][bb] = av.w;
        const float* wrow = Wx + (size_t)(h0 + hh) * IN_DIM + k0 + kq;
        float4 w0 = *(const float4*)wrow;
        float4 w1 = *(const float4*)(wrow + 4);
        Bs[kq + 0][hh] = fmaxf(w0.x, 0.f); Bs[kq + 1][hh] = fmaxf(w0.y, 0.f);
        Bs[kq + 2][hh] = fmaxf(w0.z, 0.f); Bs[kq + 3][hh] = fmaxf(w0.w, 0.f);
        Bs[kq + 4][hh] = fmaxf(w1.x, 0.f); Bs[kq + 5][hh] = fmaxf(w1.y, 0.f);
        Bs[kq + 6][hh] = fmaxf(w1.z, 0.f); Bs[kq + 7][hh] = fmaxf(w1.w, 0.f);
        __syncthreads();
#pragma unroll
        for (int kk = 0; kk < 16; kk++) {
            float4 a = *(const float4*)&As[kk][tx << 2];
            ulonglong2 wA = *(const ulonglong2*)&Bs[kk][(ty << 3)];
            ulonglong2 wB = *(const ulonglong2*)&Bs[kk][(ty << 3) + 4];
            unsigned long long a0 = pk2(a.x, a.x), a1 = pk2(a.y, a.y);
            unsigned long long a2 = pk2(a.z, a.z), a3 = pk2(a.w, a.w);
            acc[0][0] = ffma2(a0, wA.x, acc[0][0]); acc[0][1] = ffma2(a0, wA.y, acc[0][1]);
            acc[0][2] = ffma2(a0, wB.x, acc[0][2]); acc[0][3] = ffma2(a0, wB.y, acc[0][3]);
            acc[1][0] = ffma2(a1, wA.x, acc[1][0]); acc[1][1] = ffma2(a1, wA.y, acc[1][1]);
            acc[1][2] = ffma2(a1, wB.x, acc[1][2]); acc[1][3] = ffma2(a1, wB.y, acc[1][3]);
            acc[2][0] = ffma2(a2, wA.x, acc[2][0]); acc[2][1] = ffma2(a2, wA.y, acc[2][1]);
            acc[2][2] = ffma2(a2, wB.x, acc[2][2]); acc[2][3] = ffma2(a2, wB.y, acc[2][3]);
            acc[3][0] = ffma2(a3, wA.x, acc[3][0]); acc[3][1] = ffma2(a3, wA.y, acc[3][1]);
            acc[3][2] = ffma2(a3, wB.x, acc[3][2]); acc[3][3] = ffma2(a3, wB.y, acc[3][3]);
        }
    }
    float* xqT = g_xq + (size_t)t * (BATCH * HID);
#pragma unroll
    for (int i = 0; i < 4; i++) {
        int b = (tx << 2) + i;
#pragma unroll
        for (int p = 0; p < 4; p++) {
            float f0, f1; upk2(acc[i][p], f0, f1);
            int h = h0 + (ty << 3) + (p << 1);
            float2 v2 = make_float2(f0, f1);
            *(float2*)&xqT[(size_t)b * HID + h] = v2;
        }
    }
}

// ---- group barrier: 32 CTAs sharing one b-quarter (proven) ----
__device__ __forceinline__ void group_barrier(unsigned &sense, int grp) {
    sense ^= 1u;
    __syncthreads();
    if (threadIdx.x == 0) {
        unsigned* cnt  = &g_bar[grp * 64];
        unsigned* flag = &g_bar[(4 + grp) * 64];
        unsigned old = atom_add_release(cnt, 1u);
        if (old == 31u) {
            st_relaxed(cnt, 0u);
            st_release(flag, sense);
        } else {
            while (ld_acquire(flag) != sense) { }
        }
    }
    __syncthreads();
}

// ---- phase 2: persistent recurrence, 4h x 4b register tile, warp-private staging ----
// 128 CTAs x 512 threads. CTA = (hgrp 32h, b-quarter 16b). Weights resident in smem.
// Warp jg (16 warps) owns j-window [jg*64, jg*64+64): it stages its own 16b x 64j
// slice via cp.async (wait_prior + __syncwarp only -> zero cross-warp sync in the
// transfer/compute phase; producer == consumer warp). Lane: ht = lane>>2 (8),
// bt = lane&3 (4); thread tile h {ht*4..+3} x b {bt,+4,+8,+12}. f32x2 lanes pair
// consecutive j -> zero-MOV inner, 8 LDS.128 per 64 FMA.
// FIX vs R15: sRed layout is [jg][b_l*32 + h_l] stride 512 (max index 511 < 512),
// fits in the dead staging buffer; reads sRed[g*512 + tid] are conflict-free.
// sOv moved to a disjoint smem extension past sRed/staging.
extern __shared__ float rnn_smem[];
__global__ __launch_bounds__(512, 1) void rnn_kernel(const float* __restrict__ bh) {
    float* sW = rnn_smem;                                // [32][1028]
    float* sA = rnn_smem + 32 * WSTR;                    // [16][1028] staging
    unsigned long long* sRed = (unsigned long long*)sA;  // [16][512] ull = 65536 B (aliases sA)
    float* sOv = rnn_smem + 48 * WSTR;                   // [32][17] extension, disjoint

    const int cta = blockIdx.x;
    const int tid = threadIdx.x;
    const int hgrp = cta >> 2;
    const int bqg = cta & 3;
    const int b0 = bqg * 16;
    const int lane = tid & 31;
    const int jg = tid >> 5;             // warp id = j-group (16-way, 64 j each)
    const int ht = lane >> 2;            // 0..7
    const int bt = lane & 3;             // 0..3
    const int h_own = tid & 31;
    const int b_own = tid >> 5;          // 0..15
    const int hOutG = hgrp * 32 + h_own;
    const int bOut = b0 + b_own;
    const int h_s = tid >> 4;            // outAll bounce reader
    const int b_s = tid & 15;
    // warp-private staging: lane covers rows {srow0 + 2k}, cols [scol, scol+4)
    const int srow0 = lane >> 4;         // 0 or 1
    const int scol = (lane & 15) * 4;

    {   // resident weights, once per launch
        const float4* src = (const float4*)(g_eWhP2 + (size_t)hgrp * (32 * WSTR));
        float4* dst = (float4*)sW;
        for (int i = tid; i < 32 * WSTR / 4; i += 512) dst[i] = src[i];
    }

    const float bhv = bh[hOutG];
    unsigned sense = 0;
    float st;
    {   // step 0: out_prev == 0
        float xq = g_xq[(size_t)bOut * HID + hOutG];
        st = ALPHA * (xq + bhv);
        float ov = tanhf(fmaxf(st, 0.f));
        g_outT[(size_t)bOut * HID + hOutG] = ov;
        g_outAll[(size_t)hOutG * 64 + bOut] = ov;
    }
    group_barrier(sense, bqg);   // also orders sW staging

    const int jw = jg * 64;              // this warp's j-window base
    const float* w0p = sW + (size_t)(ht * 4 + 0) * WSTR + jw;
    const float* w1p = sW + (size_t)(ht * 4 + 1) * WSTR + jw;
    const float* w2p = sW + (size_t)(ht * 4 + 2) * WSTR + jw;
    const float* w3p = sW + (size_t)(ht * 4 + 3) * WSTR + jw;
    const float* a0p = sA + (size_t)(bt + 0) * WSTR + jw;
    const float* a1p = sA + (size_t)(bt + 4) * WSTR + jw;
    const float* a2p = sA + (size_t)(bt + 8) * WSTR + jw;
    const float* a3p = sA + (size_t)(bt + 12) * WSTR + jw;

    for (int t = 1; t < T_STEPS; t++) {
        {   // warp-private staging of 16b x 64j window (8 x 16B per lane)
            const float* srcB = g_outT + (size_t)(t - 1) * (BATCH * HID)
                              + (size_t)(b0 + srow0) * HID + jw + scol;
            float* dstB = sA + (size_t)srow0 * WSTR + jw + scol;
#pragma unroll
            for (int k = 0; k < 8; k++)
                __pipeline_memcpy_async(dstB + (size_t)(2 * k) * WSTR,
                                        srcB + (size_t)(2 * k) * HID, 16);
            __pipeline_commit();
        }
        float xq = g_xq[(size_t)t * (BATCH * HID) + (size_t)bOut * HID + hOutG];

        unsigned long long acc[4][4];
#pragma unroll
        for (int r = 0; r < 4; r++)
#pragma unroll
            for (int c = 0; c < 4; c++) acc[r][c] = 0ull;

        __pipeline_wait_prior(0);    // own chunks staged
        __syncwarp();                // whole warp's window staged

#pragma unroll 2
        for (int q = 0; q < 16; q++) {
            int j0 = q * 4;
            ulonglong2 wv0 = *(const ulonglong2*)(w0p + j0);
            ulonglong2 wv1 = *(const ulonglong2*)(w1p + j0);
            ulonglong2 wv2 = *(const ulonglong2*)(w2p + j0);
            ulonglong2 wv3 = *(const ulonglong2*)(w3p + j0);
            ulonglong2 av0 = *(const ulonglong2*)(a0p + j0);
            ulonglong2 av1 = *(const ulonglong2*)(a1p + j0);
            ulonglong2 av2 = *(const ulonglong2*)(a2p + j0);
            ulonglong2 av3 = *(const ulonglong2*)(a3p + j0);
            acc[0][0] = ffma2(av0.x, wv0.x, acc[0][0]); acc[0][0] = ffma2(av0.y, wv0.y, acc[0][0]);
            acc[0][1] = ffma2(av1.x, wv0.x, acc[0][1]); acc[0][1] = ffma2(av1.y, wv0.y, acc[0][1]);
            acc[0][2] = ffma2(av2.x, wv0.x, acc[0][2]); acc[0][2] = ffma2(av2.y, wv0.y, acc[0][2]);
            acc[0][3] = ffma2(av3.x, wv0.x, acc[0][3]); acc[0][3] = ffma2(av3.y, wv0.y, acc[0][3]);
            acc[1][0] = ffma2(av0.x, wv1.x, acc[1][0]); acc[1][0] = ffma2(av0.y, wv1.y, acc[1][0]);
            acc[1][1] = ffma2(av1.x, wv1.x, acc[1][1]); acc[1][1] = ffma2(av1.y, wv1.y, acc[1][1]);
            acc[1][2] = ffma2(av2.x, wv1.x, acc[1][2]); acc[1][2] = ffma2(av2.y, wv1.y, acc[1][2]);
            acc[1][3] = ffma2(av3.x, wv1.x, acc[1][3]); acc[1][3] = ffma2(av3.y, wv1.y, acc[1][3]);
            acc[2][0] = ffma2(av0.x, wv2.x, acc[2][0]); acc[2][0] = ffma2(av0.y, wv2.y, acc[2][0]);
            acc[2][1] = ffma2(av1.x, wv2.x, acc[2][1]); acc[2][1] = ffma2(av1.y, wv2.y, acc[2][1]);
            acc[2][2] = ffma2(av2.x, wv2.x, acc[2][2]); acc[2][2] = ffma2(av2.y, wv2.y, acc[2][2]);
            acc[2][3] = ffma2(av3.x, wv2.x, acc[2][3]); acc[2][3] = ffma2(av3.y, wv2.y, acc[2][3]);
            acc[3][0] = ffma2(av0.x, wv3.x, acc[3][0]); acc[3][0] = ffma2(av0.y, wv3.y, acc[3][0]);
            acc[3][1] = ffma2(av1.x, wv3.x, acc[3][1]); acc[3][1] = ffma2(av1.y, wv3.y, acc[3][1]);
            acc[3][2] = ffma2(av2.x, wv3.x, acc[3][2]); acc[3][2] = ffma2(av2.y, wv3.y, acc[3][2]);
            acc[3][3] = ffma2(av3.x, wv3.x, acc[3][3]); acc[3][3] = ffma2(av3.y, wv3.y, acc[3][3]);
        }

        __syncthreads();   // ALL warps done reading sA (sRed aliases it)
        // sRed: [jg][b_l*32 + h_l], h_l = ht*4+r (0..31), b_l = bt+4c (0..15)
#pragma unroll
        for (int r = 0; r < 4; r++)
#pragma unroll
            for (int c = 0; c < 4; c++)
                sRed[jg * 512 + (bt + 4 * c) * 32 + (ht * 4 + r)] = acc[r][c];
        __syncthreads();
        unsigned long long s = sRed[tid];          // oid = b_own*32 + h_own = tid
#pragma unroll
        for (int g = 1; g < 16; g++) s = fadd2(s, sRed[g * 512 + tid]);
        float f0, f1; upk2(s, f0, f1);
        float r = f0 + f1;

        st = OMALPHA * st + ALPHA * (xq + r + bhv);
        float ov = tanhf(fmaxf(st, 0.f));
        g_outT[(size_t)t * (BATCH * HID) + (size_t)bOut * HID + hOutG] = ov;  // coalesced
        sOv[h_own * 17 + b_own] = ov;    // disjoint extension region
        __syncthreads();
        g_outAll[(size_t)t * (HID * BATCH) + (size_t)(hgrp * 32 + h_s) * 64 + b0 + b_s]
            = sOv[h_s * 17 + b_s];       // coalesced

        group_barrier(sense, bqg);       // 1000 flips/group (even) -> replay safe
    }
}

// ---- phase 3 (proven): y[t][b][o] = sum_j out[t][j][b]*eWoT[j][o]+bias
__global__ __launch_bounds__(256) void readout_kernel(const float* __restrict__ bo,
                                                      const float* __restrict__ bv,
                                                      float* __restrict__ y) {
    __shared__ float outS[64][64];
    const int t = blockIdx.x;
    const int tid = threadIdx.x;
    const int tx = tid & 15, ty = tid >> 4;
    const int b4 = tx * 4, o4 = ty * 4;
    const float* outT = g_outAll + (size_t)t * (HID * BATCH);

    unsigned long long acc[4][2];
#pragma unroll
    for (int i = 0; i < 4; i++) { acc[i][0] = 0ull; acc[i][1] = 0ull; }
    float accv[4] = {0.f, 0.f, 0.f, 0.f};

    for (int tile = 0; tile < 16; tile++) {
        __syncthreads();
#pragma unroll
        for (int k = 0; k < 4; k++) {
            int fid = tid + k * 256;
            ((float4*)&outS[0][0])[fid] = ((const float4*)(outT + (size_t)tile * 4096))[fid];
        }
        __syncthreads();
#pragma unroll 4
        for (int jj = 0; jj < 64; jj++) {
            int j = tile * 64 + jj;
            float4 ov = *(const float4*)&outS[jj][b4];
            ulonglong2 wq = __ldg((const ulonglong2*)(g_eWoT + (size_t)j * OPAD + o4));
            unsigned long long a0 = pk2(ov.x, ov.x), a1 = pk2(ov.y, ov.y);
            unsigned long long a2 = pk2(ov.z, ov.z), a3 = pk2(ov.w, ov.w);
            acc[0][0] = ffma2(a0, wq.x, acc[0][0]); acc[0][1] = ffma2(a0, wq.y, acc[0][1]);
            acc[1][0] = ffma2(a1, wq.x, acc[1][0]); acc[1][1] = ffma2(a1, wq.y, acc[1][1]);
            acc[2][0] = ffma2(a2, wq.x, acc[2][0]); acc[2][1] = ffma2(a2, wq.y, acc[2][1]);
            acc[3][0] = ffma2(a3, wq.x, acc[3][0]); acc[3][1] = ffma2(a3, wq.y, acc[3][1]);
            if (ty == 0) {
                float w64 = __ldg(g_eWoT + (size_t)j * OPAD + 64);
                accv[0] += ov.x * w64; accv[1] += ov.y * w64;
                accv[2] += ov.z * w64; accv[3] += ov.w * w64;
            }
        }
    }

    float* yt = y + (size_t)t * (BATCH * NY);
    const float bo0 = bo[o4], bo1 = bo[o4 + 1], bo2 = bo[o4 + 2], bo3 = bo[o4 + 3];
#pragma unroll
    for (int i = 0; i < 4; i++) {
        float f0, f1, f2, f3;
        upk2(acc[i][0], f0, f1);
        upk2(acc[i][1], f2, f3);
        float* yr = yt + (size_t)(b4 + i) * NY;
        yr[o4 + 0] = f0 + bo0; yr[o4 + 1] = f1 + bo1;
        yr[o4 + 2] = f2 + bo2; yr[o4 + 3] = f3 + bo3;
        if (ty == 0) yr[64] = accv[i] + bv[0];
    }
}

extern "C" void kernel_launch(void* const* d_in, const int* in_sizes, int n_in,
                              void* d_out, int out_size) {
    const float* x  = (const float*)d_in[0];
    const float* Wx = (const float*)d_in[1];
    const float* Wh = (const float*)d_in[2];
    const float* bh = (const float*)d_in[3];
    const float* Wo = (const float*)d_in[4];
    const float* bo = (const float*)d_in[5];
    const float* Wv = (const float*)d_in[6];
    const float* bv = (const float*)d_in[7];
    float* y = (float*)d_out;
    (void)in_sizes; (void)n_in; (void)out_size;

    {
        int total = HID * HID + NY * HID;
        prep_kernel<<<(total + 255) / 256, 256>>>(Wh, Wo, Wv);
    }
    xproj_kernel<<<dim3(HID / 128, T_STEPS), 256>>>(x, Wx);
    noop_kernel<<<1, 32>>>();   // keeps rnn_kernel in the profiled (4th) slot
    // 32*1028 weights + 16*1028 staging (sRed aliases) + 544 sOv + pad = 199680 B
    static const int RNN_SMEM = (48 * WSTR + 576) * 4;
    cudaFuncSetAttribute(rnn_kernel, cudaFuncAttributeMaxDynamicSharedMemorySize, RNN_SMEM);
    rnn_kernel<<<NCTA, 512, RNN_SMEM>>>(bh);
    readout_kernel<<<T_STEPS, 256>>>(bo, bv, y);
}